// round 3
// baseline (speedup 1.0000x reference)
#include <cuda_runtime.h>
#include <cuda_bf16.h>
#include <cstdint>

#define NNODES 50000
#define NEDGES 640000
#define MDIM 128
#define DDIM 128
#define HDIM 64

// ---------------- device scratch (static, no runtime alloc) ----------------
__device__ float g_P[(size_t)NNODES * HDIM];     // per-node projected features + b1
__device__ float g_sumw[NNODES];                 // sum of weights per node
__device__ __nv_bfloat16 g_W1m[HDIM * MDIM];     // W1[:, :128]  (message half), bf16
__device__ __nv_bfloat16 g_W1t[HDIM * DDIM];     // W1[:, 128:]  (node half),    bf16

// ---------------- shared memory layout ----------------
#define SM_VEC 0
#define SM_WT 256
#define SM_TG 768
#define SM_A 1280
#define SM_B (1280 + 34816)
#define SMEM_BYTES (SM_B + 17408)
#define LDA 136              // bf16 elements per row (8-elem pad -> conflict-free ldmatrix)
#define LDAB (LDA * 2)       // 272 bytes

// ---------------- helpers ----------------
__device__ __forceinline__ uint32_t smem_u32(const void* p) {
    uint32_t a;
    asm("{ .reg .u64 t; cvta.to.shared.u64 t, %1; cvt.u32.u64 %0, t; }" : "=r"(a) : "l"(p));
    return a;
}

__device__ __forceinline__ void ldm4(uint32_t& r0, uint32_t& r1, uint32_t& r2, uint32_t& r3,
                                     uint32_t addr) {
    asm volatile("ldmatrix.sync.aligned.m8n8.x4.shared.b16 {%0,%1,%2,%3}, [%4];"
                 : "=r"(r0), "=r"(r1), "=r"(r2), "=r"(r3) : "r"(addr));
}

__device__ __forceinline__ void mma16816(float* c, uint32_t a0, uint32_t a1, uint32_t a2,
                                         uint32_t a3, uint32_t b0, uint32_t b1) {
    asm volatile(
        "mma.sync.aligned.m16n8k16.row.col.f32.bf16.bf16.f32 "
        "{%0,%1,%2,%3}, {%4,%5,%6,%7}, {%8,%9}, {%0,%1,%2,%3};"
        : "+f"(c[0]), "+f"(c[1]), "+f"(c[2]), "+f"(c[3])
        : "r"(a0), "r"(a1), "r"(a2), "r"(a3), "r"(b0), "r"(b1));
}

__device__ __forceinline__ void red_add_v4(float* addr, float4 v) {
    asm volatile("red.global.add.v4.f32 [%0], {%1,%2,%3,%4};"
                 :: "l"(addr), "f"(v.x), "f"(v.y), "f"(v.z), "f"(v.w) : "memory");
}

// tanh-form gelu via MUFU (max dev from exact erf-gelu ~3e-4; cheap: ~10 instr, 2 MUFU)
__device__ __forceinline__ float gelu_fast(float x) {
    float t = 1.5957692f * fmaf(0.044715f * x, x * x, x);
    return __fdividef(x, 1.0f + __expf(-t));
}

// ---------------- shared 128x64 K=128 bf16 GEMM (A:[128][K] smem, B:[64][K] smem) ----
// Result written to smem C float [128][68] at SM_A (overwrites A after a syncthreads).
__device__ __forceinline__ void gemm_128x64(char* smem, uint32_t sb, int wid, int lid) {
    float c[2][8][4];
#pragma unroll
    for (int t = 0; t < 2; t++)
#pragma unroll
        for (int n = 0; n < 8; n++)
#pragma unroll
            for (int j = 0; j < 4; j++) c[t][n][j] = 0.f;

    const int lrow = lid & 15;
    const int lcol = (lid >> 4) * 8;

#pragma unroll
    for (int k = 0; k < 8; k++) {
        const uint32_t kc = (uint32_t)(k * 16 + lcol) * 2;
        uint32_t af[2][4], bf[4][4];
        uint32_t A0 = sb + SM_A + (uint32_t)(wid * 32 + lrow) * LDAB + kc;
        ldm4(af[0][0], af[0][1], af[0][2], af[0][3], A0);
        ldm4(af[1][0], af[1][1], af[1][2], af[1][3], A0 + 16 * LDAB);
#pragma unroll
        for (int g = 0; g < 4; g++) {
            uint32_t B0 = sb + SM_B + (uint32_t)(g * 16 + lrow) * LDAB + kc;
            ldm4(bf[g][0], bf[g][1], bf[g][2], bf[g][3], B0);
        }
#pragma unroll
        for (int t = 0; t < 2; t++)
#pragma unroll
            for (int n = 0; n < 8; n++)
                mma16816(c[t][n], af[t][0], af[t][1], af[t][2], af[t][3],
                         bf[n >> 1][n & 1], bf[n >> 1][(n & 1) + 2]);
    }
    __syncthreads();   // everyone done reading A/B before C overwrites A
#pragma unroll
    for (int t = 0; t < 2; t++) {
        int r0 = wid * 32 + t * 16 + (lid >> 2);
#pragma unroll
        for (int n = 0; n < 8; n++) {
            int col = n * 8 + (lid & 3) * 2;
            *(float2*)(smem + SM_A + r0 * LDAB + col * 4) = make_float2(c[t][n][0], c[t][n][1]);
            *(float2*)(smem + SM_A + (r0 + 8) * LDAB + col * 4) = make_float2(c[t][n][2], c[t][n][3]);
        }
    }
    __syncthreads();
}

// ---------------- prep: W1 fp32 -> bf16 halves ----------------
__global__ void prep_kernel(const float* __restrict__ W1) {
    int i = blockIdx.x * blockDim.x + threadIdx.x;
    if (i < HDIM * MDIM) {
        int row = i >> 7, k = i & 127;
        g_W1m[i] = __float2bfloat16(W1[row * 256 + k]);
        g_W1t[i] = __float2bfloat16(W1[row * 256 + 128 + k]);
    }
}

// ---------------- zero d_out + sumw ----------------
__global__ void zero_kernel(float* __restrict__ agg) {
    int i = blockIdx.x * blockDim.x + threadIdx.x;
    int stride = gridDim.x * blockDim.x;
    float4 z = make_float4(0.f, 0.f, 0.f, 0.f);
    for (int j = i; j < NNODES * MDIM / 4; j += stride) ((float4*)agg)[j] = z;
    for (int j = i; j < NNODES; j += stride) g_sumw[j] = 0.f;
}

// ---------------- P = node_features @ W1t^T + b1 ----------------
__global__ void __launch_bounds__(128) pnode_kernel(const float* __restrict__ nf,
                                                    const float* __restrict__ b1) {
    extern __shared__ char smem[];
    const uint32_t sb = smem_u32(smem);
    const int tid = threadIdx.x, wid = tid >> 5, lid = tid & 31;
    const int base = blockIdx.x * 128;

    // B = W1t bf16 [64][136]
    for (int i = tid; i < HDIM * DDIM / 2; i += 128) {
        int row = i >> 6, kp = i & 63;
        *(uint32_t*)(smem + SM_B + row * LDAB + kp * 4) = *(const uint32_t*)(g_W1t + row * DDIM + kp * 2);
    }
    // A = node rows fp32->bf16 [128][136] (zero-pad past NNODES)
    const float4* nf4 = (const float4*)nf;
    for (int i = tid; i < 128 * 32; i += 128) {
        int row = i >> 5, c4 = i & 31;
        int node = base + row;
        float4 v = (node < NNODES) ? nf4[(size_t)node * 32 + c4] : make_float4(0.f, 0.f, 0.f, 0.f);
        __nv_bfloat162 lo = __floats2bfloat162_rn(v.x, v.y);
        __nv_bfloat162 hi = __floats2bfloat162_rn(v.z, v.w);
        uint2 u;
        u.x = *(uint32_t*)&lo;
        u.y = *(uint32_t*)&hi;
        *(uint2*)(smem + SM_A + row * LDAB + c4 * 8) = u;
    }
    if (tid < 64) ((float*)(smem + SM_VEC))[tid] = b1[tid];
    __syncthreads();

    gemm_128x64(smem, sb, wid, lid);

    int node = base + tid;
    if (node < NNODES) {
        const float* sb1 = (const float*)(smem + SM_VEC);
        const float* Crow = (const float*)(smem + SM_A + tid * LDAB);
        float4* Pr = (float4*)(g_P + (size_t)node * HDIM);
#pragma unroll
        for (int j = 0; j < 16; j++) {
            float4 cv = ((const float4*)Crow)[j];
            Pr[j] = make_float4(cv.x + sb1[4 * j], cv.y + sb1[4 * j + 1],
                                cv.z + sb1[4 * j + 2], cv.w + sb1[4 * j + 3]);
        }
    }
}

// ---------------- main edge kernel: score + weighted scatter ----------------
__global__ void __launch_bounds__(128) edge_kernel(const float* __restrict__ msg,
                                                   const int* __restrict__ tgt,
                                                   const float* __restrict__ W2,
                                                   float* __restrict__ agg) {
    extern __shared__ char smem[];
    const uint32_t sb = smem_u32(smem);
    const int tid = threadIdx.x, wid = tid >> 5, lid = tid & 31;
    const int base = blockIdx.x * 128;

    // B = W1m bf16 [64][136]
    for (int i = tid; i < HDIM * MDIM / 2; i += 128) {
        int row = i >> 6, kp = i & 63;
        *(uint32_t*)(smem + SM_B + row * LDAB + kp * 4) = *(const uint32_t*)(g_W1m + row * MDIM + kp * 2);
    }
    // A = messages fp32->bf16 [128][136]
    const float4* m4 = (const float4*)msg + (size_t)base * 32;
    for (int i = tid; i < 128 * 32; i += 128) {
        int row = i >> 5, c4 = i & 31;
        float4 v = m4[row * 32 + c4];
        __nv_bfloat162 lo = __floats2bfloat162_rn(v.x, v.y);
        __nv_bfloat162 hi = __floats2bfloat162_rn(v.z, v.w);
        uint2 u;
        u.x = *(uint32_t*)&lo;
        u.y = *(uint32_t*)&hi;
        *(uint2*)(smem + SM_A + row * LDAB + c4 * 8) = u;
    }
    if (tid < 64) ((float*)(smem + SM_VEC))[tid] = W2[tid];
    const int t_own = tgt[base + tid];          // int32 indices (JAX demotes int64)
    ((int*)(smem + SM_TG))[tid] = t_own;
    __syncthreads();

    gemm_128x64(smem, sb, wid, lid);

    // score: r = sum_j W2[j] * gelu(mproj[j] + P[target][j])
    const float* sW2 = (const float*)(smem + SM_VEC);
    const float4* Crow = (const float4*)(smem + SM_A + tid * LDAB);
    const float4* Pr = (const float4*)(g_P + (size_t)t_own * HDIM);
    float r = 0.f;
#pragma unroll
    for (int j = 0; j < 16; j++) {
        float4 cv = Crow[j];
        float4 p = Pr[j];
        r = fmaf(gelu_fast(cv.x + p.x), sW2[4 * j + 0], r);
        r = fmaf(gelu_fast(cv.y + p.y), sW2[4 * j + 1], r);
        r = fmaf(gelu_fast(cv.z + p.z), sW2[4 * j + 2], r);
        r = fmaf(gelu_fast(cv.w + p.w), sW2[4 * j + 3], r);
    }
    float w = __fdividef(1.f, 1.f + __expf(-r));
    ((float*)(smem + SM_WT))[tid] = w;
    atomicAdd(&g_sumw[t_own], w);
    __syncthreads();

    // weighted scatter: warp per edge, lane l handles float4 l (coalesced reads, v4 reds)
    const float* sw = (const float*)(smem + SM_WT);
    const int* st = (const int*)(smem + SM_TG);
    for (int e = wid; e < 128; e += 4) {
        float we = sw[e];
        int te = st[e];
        float4 v = m4[e * 32 + lid];   // L1/L2 hit (loaded above)
        red_add_v4(agg + (size_t)te * 128 + lid * 4,
                   make_float4(v.x * we, v.y * we, v.z * we, v.w * we));
    }
}

// ---------------- finalize: divide by sumw + LayerNorm ----------------
__global__ void finalize_kernel(float* __restrict__ agg,
                                const float* __restrict__ gamma,
                                const float* __restrict__ beta) {
    int wid = threadIdx.x >> 5, lid = threadIdx.x & 31;
    int node = blockIdx.x * (blockDim.x >> 5) + wid;
    if (node >= NNODES) return;
    float inv = __fdividef(1.f, g_sumw[node] + 1e-8f);
    float4 v = ((const float4*)(agg + (size_t)node * 128))[lid];
    v.x *= inv; v.y *= inv; v.z *= inv; v.w *= inv;
    float s = v.x + v.y + v.z + v.w;
#pragma unroll
    for (int o = 16; o; o >>= 1) s += __shfl_xor_sync(0xffffffff, s, o);
    float mu = s * (1.f / 128.f);
    float dx = v.x - mu, dy = v.y - mu, dz = v.z - mu, dw = v.w - mu;
    float q = dx * dx + dy * dy + dz * dz + dw * dw;
#pragma unroll
    for (int o = 16; o; o >>= 1) q += __shfl_xor_sync(0xffffffff, q, o);
    float rs = rsqrtf(q * (1.f / 128.f) + 1e-5f);
    float4 g = ((const float4*)gamma)[lid];
    float4 b = ((const float4*)beta)[lid];
    ((float4*)(agg + (size_t)node * 128))[lid] =
        make_float4(dx * rs * g.x + b.x, dy * rs * g.y + b.y,
                    dz * rs * g.z + b.z, dw * rs * g.w + b.w);
}

// ---------------- launch ----------------
extern "C" void kernel_launch(void* const* d_in, const int* in_sizes, int n_in,
                              void* d_out, int out_size) {
    const float* msg = (const float*)d_in[0];
    const int* tgt = (const int*)d_in[1];
    const float* nf = (const float*)d_in[2];
    int wi = 3;
    for (int i = 3; i < n_in; i++) {
        if (in_sizes[i] == HDIM * (MDIM + DDIM)) { wi = i; break; }
    }
    const float* W1 = (const float*)d_in[wi];
    const float* b1 = (const float*)d_in[wi + 1];
    const float* W2 = (const float*)d_in[wi + 2];
    const float* gamma = (const float*)d_in[wi + 3];
    const float* beta = (const float*)d_in[wi + 4];
    float* agg = (float*)d_out;

    cudaFuncSetAttribute(pnode_kernel, cudaFuncAttributeMaxDynamicSharedMemorySize, SMEM_BYTES);
    cudaFuncSetAttribute(edge_kernel, cudaFuncAttributeMaxDynamicSharedMemorySize, SMEM_BYTES);

    prep_kernel<<<32, 256>>>(W1);
    zero_kernel<<<512, 256>>>(agg);
    pnode_kernel<<<(NNODES + 127) / 128, 128, SMEM_BYTES>>>(nf, b1);
    edge_kernel<<<NEDGES / 128, 128, SMEM_BYTES>>>(msg, tgt, W2, agg);
    finalize_kernel<<<(NNODES + 7) / 8, 256>>>(agg, gamma, beta);
}